// round 8
// baseline (speedup 1.0000x reference)
#include <cuda_runtime.h>
#include <cstdint>

#define NN 100000
#define INF_ 128
#define OUTF 64
#define NE 1600000
#define CAP 64   // per-row bucket capacity (mean degree 16, Poisson)

// Static device scratch (allocation-free per harness rules)
__device__ float g_support[(size_t)NN * OUTF];       // 25.6 MB
__device__ int   g_cursor[NN];                       // degree counters
__device__ int2  g_bucket[(size_t)NN * CAP];         // 51.2 MB (col, val-bits)
__device__ int   g_ovf_cnt;
__device__ int3  g_ovf[NE];                          // overflow (row, col, val-bits)

// ---------------------------------------------------------------------------
// support = X @ W.  Tiled fp32 SIMT GEMM (proven).  Also zeroes g_cursor and
// g_ovf_cnt (safe: fill launches after this kernel completes in stream order).
// ---------------------------------------------------------------------------
__global__ __launch_bounds__(256, 2)
void gemm_kernel(const float* __restrict__ x, const float* __restrict__ w, int n) {
    __shared__ float xs[64][132];
    __shared__ float ws[128][68];

    const int tid  = threadIdx.x;
    const int brow = blockIdx.x * 64;

    // Fused: zero the per-row cursors + overflow counter
    {
        int gi = blockIdx.x * 256 + tid;
        if (gi < NN) g_cursor[gi] = 0;
        if (gi == 0) g_ovf_cnt = 0;
    }

#pragma unroll
    for (int it = 0; it < 8; it++) {
        int i = tid + it * 256;
        int k = i >> 4;
        int c = (i & 15) << 2;
        float4 v = *(const float4*)&w[k * OUTF + c];
        *(float4*)&ws[k][c] = v;
    }
#pragma unroll
    for (int it = 0; it < 8; it++) {
        int i = tid + it * 256;
        int r = i >> 5;
        int k = (i & 31) << 2;
        int grow = brow + r;
        float4 v = make_float4(0.f, 0.f, 0.f, 0.f);
        if (grow < n) v = *(const float4*)&x[(size_t)grow * INF_ + k];
        *(float4*)&xs[r][k] = v;
    }
    __syncthreads();

    const int r0 = (tid >> 4) << 2;
    const int c0 = (tid & 15) << 2;

    float acc[4][4] = {};
#pragma unroll 4
    for (int k = 0; k < 128; k++) {
        float a0 = xs[r0 + 0][k];
        float a1 = xs[r0 + 1][k];
        float a2 = xs[r0 + 2][k];
        float a3 = xs[r0 + 3][k];
        float4 b = *(float4*)&ws[k][c0];
        acc[0][0] += a0 * b.x; acc[0][1] += a0 * b.y; acc[0][2] += a0 * b.z; acc[0][3] += a0 * b.w;
        acc[1][0] += a1 * b.x; acc[1][1] += a1 * b.y; acc[1][2] += a1 * b.z; acc[1][3] += a1 * b.w;
        acc[2][0] += a2 * b.x; acc[2][1] += a2 * b.y; acc[2][2] += a2 * b.z; acc[2][3] += a2 * b.w;
        acc[3][0] += a3 * b.x; acc[3][1] += a3 * b.y; acc[3][2] += a3 * b.z; acc[3][3] += a3 * b.w;
    }

#pragma unroll
    for (int i = 0; i < 4; i++) {
        int grow = brow + r0 + i;
        if (grow < n) {
            float4 v = make_float4(acc[i][0], acc[i][1], acc[i][2], acc[i][3]);
            *(float4*)&g_support[(size_t)grow * OUTF + c0] = v;
        }
    }
}

// ---------------------------------------------------------------------------
// Fill: scatter edges into fixed-capacity per-row buckets (no prefix sum).
// Overflow (degree > CAP) goes to a spill list handled after pull.
// ---------------------------------------------------------------------------
__global__ void fill_kernel(const int* __restrict__ erow, const int* __restrict__ ecol,
                            const float* __restrict__ evals) {
    int e = blockIdx.x * blockDim.x + threadIdx.x;
    if (e < NE) {
        int r = __ldg(&erow[e]);
        int c = __ldg(&ecol[e]);
        int v = __float_as_int(__ldg(&evals[e]));
        int pos = atomicAdd(&g_cursor[r], 1);
        if (pos < CAP) {
            g_bucket[(size_t)r * CAP + pos] = make_int2(c, v);
        } else {
            int o = atomicAdd(&g_ovf_cnt, 1);
            g_ovf[o] = make_int3(r, c, v);
        }
    }
}

// ---------------------------------------------------------------------------
// Pull: one warp per destination row.  Lanes cooperatively load the row's
// (col,val) bucket, shfl-broadcast, gather float2 per lane from support with
// MLP=8, accumulate in registers, single plain store (bias fused, no atomics).
// ---------------------------------------------------------------------------
__global__ __launch_bounds__(256)
void pull_kernel(const float* __restrict__ bias, float* __restrict__ out) {
    int wid_g = (blockIdx.x * 256 + threadIdx.x) >> 5;
    int lane  = threadIdx.x & 31;
    if (wid_g >= NN) return;

    const int row = wid_g;
    int len = g_cursor[row];
    len = len < CAP ? len : CAP;
    const int2* __restrict__ plist = g_bucket + (size_t)row * CAP;
    const int fo = lane * 2;

    float2 acc = *(const float2*)&bias[fo];

    for (int base = 0; base < len; base += 32) {
        int rem = len - base;
        int m   = rem < 32 ? rem : 32;
        int2 p = make_int2(0, 0);
        if (lane < m) p = plist[base + lane];

        int j = 0;
        // MLP=8: eight independent gathers in flight
        for (; j + 8 <= m; j += 8) {
            int c0 = __shfl_sync(0xffffffffu, p.x, j + 0);
            int c1 = __shfl_sync(0xffffffffu, p.x, j + 1);
            int c2 = __shfl_sync(0xffffffffu, p.x, j + 2);
            int c3 = __shfl_sync(0xffffffffu, p.x, j + 3);
            int c4 = __shfl_sync(0xffffffffu, p.x, j + 4);
            int c5 = __shfl_sync(0xffffffffu, p.x, j + 5);
            int c6 = __shfl_sync(0xffffffffu, p.x, j + 6);
            int c7 = __shfl_sync(0xffffffffu, p.x, j + 7);

            float2 s0 = *(const float2*)&g_support[(size_t)c0 * OUTF + fo];
            float2 s1 = *(const float2*)&g_support[(size_t)c1 * OUTF + fo];
            float2 s2 = *(const float2*)&g_support[(size_t)c2 * OUTF + fo];
            float2 s3 = *(const float2*)&g_support[(size_t)c3 * OUTF + fo];
            float2 s4 = *(const float2*)&g_support[(size_t)c4 * OUTF + fo];
            float2 s5 = *(const float2*)&g_support[(size_t)c5 * OUTF + fo];
            float2 s6 = *(const float2*)&g_support[(size_t)c6 * OUTF + fo];
            float2 s7 = *(const float2*)&g_support[(size_t)c7 * OUTF + fo];

            float v0 = __int_as_float(__shfl_sync(0xffffffffu, p.y, j + 0));
            float v1 = __int_as_float(__shfl_sync(0xffffffffu, p.y, j + 1));
            float v2 = __int_as_float(__shfl_sync(0xffffffffu, p.y, j + 2));
            float v3 = __int_as_float(__shfl_sync(0xffffffffu, p.y, j + 3));
            float v4 = __int_as_float(__shfl_sync(0xffffffffu, p.y, j + 4));
            float v5 = __int_as_float(__shfl_sync(0xffffffffu, p.y, j + 5));
            float v6 = __int_as_float(__shfl_sync(0xffffffffu, p.y, j + 6));
            float v7 = __int_as_float(__shfl_sync(0xffffffffu, p.y, j + 7));

            acc.x += s0.x * v0; acc.y += s0.y * v0;
            acc.x += s1.x * v1; acc.y += s1.y * v1;
            acc.x += s2.x * v2; acc.y += s2.y * v2;
            acc.x += s3.x * v3; acc.y += s3.y * v3;
            acc.x += s4.x * v4; acc.y += s4.y * v4;
            acc.x += s5.x * v5; acc.y += s5.y * v5;
            acc.x += s6.x * v6; acc.y += s6.y * v6;
            acc.x += s7.x * v7; acc.y += s7.y * v7;
        }
        for (; j < m; j++) {
            int   c = __shfl_sync(0xffffffffu, p.x, j);
            float v = __int_as_float(__shfl_sync(0xffffffffu, p.y, j));
            float2 s = *(const float2*)&g_support[(size_t)c * OUTF + fo];
            acc.x += s.x * v; acc.y += s.y * v;
        }
    }

    *(float2*)&out[(size_t)row * OUTF + fo] = acc;
}

// ---------------------------------------------------------------------------
// Overflow fixup: apply spilled edges (degree > CAP) with vector reductions.
// Normally zero iterations. Runs after pull (pull does plain stores).
// ---------------------------------------------------------------------------
__global__ void ovf_kernel(float* __restrict__ out) {
    int cnt = g_ovf_cnt;
    int total = cnt * 16;
    for (int i = blockIdx.x * blockDim.x + threadIdx.x; i < total;
         i += gridDim.x * blockDim.x) {
        int e = i >> 4;
        int f = (i & 15) << 2;
        int3 t = g_ovf[e];
        float v = __int_as_float(t.z);
        float4 s = *(const float4*)&g_support[(size_t)t.y * OUTF + f];
        float* dst = &out[(size_t)t.x * OUTF + f];
        asm volatile("red.global.add.v4.f32 [%0], {%1, %2, %3, %4};"
                     :: "l"(dst), "f"(s.x * v), "f"(s.y * v), "f"(s.z * v), "f"(s.w * v)
                     : "memory");
    }
}

// ---------------------------------------------------------------------------
extern "C" void kernel_launch(void* const* d_in, const int* in_sizes, int n_in,
                              void* d_out, int out_size) {
    const float* x     = (const float*)d_in[0];   // [100000,128]
    const float* w     = (const float*)d_in[1];   // [128,64]
    const float* bias  = (const float*)d_in[2];   // [64]
    const int*   erow  = (const int*)  d_in[3];   // [1.6M]
    const int*   ecol  = (const int*)  d_in[4];   // [1.6M]
    const float* evals = (const float*)d_in[5];   // [1.6M]
    float* out = (float*)d_out;                   // [100000,64]

    const int n = in_sizes[0] / INF_;             // 100000

    // support = X @ W (SIMT fp32) + zero cursors
    gemm_kernel<<<(n + 63) / 64, 256>>>(x, w, n);

    // Bucket the edges by destination row (no prefix sum)
    fill_kernel<<<(NE + 255) / 256, 256>>>(erow, ecol, evals);

    // Pull: out[row] = bias + sum(support[col] * val)
    {
        long long threads = (long long)NN * 32;
        int blocks = (int)((threads + 255) / 256);
        pull_kernel<<<blocks, 256>>>(bias, out);
    }

    // Apply overflow edges (rare; usually zero work)
    ovf_kernel<<<64, 256>>>(out);
}

// round 9
// speedup vs baseline: 1.4075x; 1.4075x over previous
#include <cuda_runtime.h>
#include <cstdint>

#define NN 100000
#define INF_ 128
#define OUTF 64
#define NE 1600000
#define NCHUNK ((NN + 511) / 512)   // 196

// Static device scratch (allocation-free per harness rules)
__device__ float g_support[(size_t)NN * OUTF];   // 25.6 MB
__device__ int   g_counts[NN];
__device__ int   g_rowstart[NN];
__device__ int   g_cursor[NN];
__device__ int   g_chunksum[NCHUNK];
__device__ int2  g_packed[NE];                   // 12.8 MB (col, val-bits) grouped by row

// ---------------------------------------------------------------------------
// support = X @ W.  Tiled fp32 SIMT GEMM (proven).  Also zeroes g_counts
// (safe: hist launches after this kernel completes in stream order).
// ---------------------------------------------------------------------------
__global__ __launch_bounds__(256, 2)
void gemm_kernel(const float* __restrict__ x, const float* __restrict__ w, int n) {
    __shared__ float xs[64][132];
    __shared__ float ws[128][68];

    const int tid  = threadIdx.x;
    const int brow = blockIdx.x * 64;

    // Fused: zero the histogram counters
    {
        int gi = blockIdx.x * 256 + tid;
        if (gi < NN) g_counts[gi] = 0;
    }

#pragma unroll
    for (int it = 0; it < 8; it++) {
        int i = tid + it * 256;
        int k = i >> 4;
        int c = (i & 15) << 2;
        float4 v = *(const float4*)&w[k * OUTF + c];
        *(float4*)&ws[k][c] = v;
    }
#pragma unroll
    for (int it = 0; it < 8; it++) {
        int i = tid + it * 256;
        int r = i >> 5;
        int k = (i & 31) << 2;
        int grow = brow + r;
        float4 v = make_float4(0.f, 0.f, 0.f, 0.f);
        if (grow < n) v = *(const float4*)&x[(size_t)grow * INF_ + k];
        *(float4*)&xs[r][k] = v;
    }
    __syncthreads();

    const int r0 = (tid >> 4) << 2;
    const int c0 = (tid & 15) << 2;

    float acc[4][4] = {};
#pragma unroll 4
    for (int k = 0; k < 128; k++) {
        float a0 = xs[r0 + 0][k];
        float a1 = xs[r0 + 1][k];
        float a2 = xs[r0 + 2][k];
        float a3 = xs[r0 + 3][k];
        float4 b = *(float4*)&ws[k][c0];
        acc[0][0] += a0 * b.x; acc[0][1] += a0 * b.y; acc[0][2] += a0 * b.z; acc[0][3] += a0 * b.w;
        acc[1][0] += a1 * b.x; acc[1][1] += a1 * b.y; acc[1][2] += a1 * b.z; acc[1][3] += a1 * b.w;
        acc[2][0] += a2 * b.x; acc[2][1] += a2 * b.y; acc[2][2] += a2 * b.z; acc[2][3] += a2 * b.w;
        acc[3][0] += a3 * b.x; acc[3][1] += a3 * b.y; acc[3][2] += a3 * b.z; acc[3][3] += a3 * b.w;
    }

#pragma unroll
    for (int i = 0; i < 4; i++) {
        int grow = brow + r0 + i;
        if (grow < n) {
            float4 v = make_float4(acc[i][0], acc[i][1], acc[i][2], acc[i][3]);
            *(float4*)&g_support[(size_t)grow * OUTF + c0] = v;
        }
    }
}

// ---------------------------------------------------------------------------
// Build phase: counting sort of edges by destination row
// ---------------------------------------------------------------------------
__global__ void hist_kernel(const int* __restrict__ erow) {
    int e = blockIdx.x * blockDim.x + threadIdx.x;
    if (e < NE) atomicAdd(&g_counts[__ldg(&erow[e])], 1);
}

// S1: per-chunk (512) reduction of counts -> g_chunksum[b]
__global__ __launch_bounds__(512)
void scan1_kernel() {
    __shared__ int s[512];
    int t = threadIdx.x, b = blockIdx.x;
    int i = b * 512 + t;
    s[t] = (i < NN) ? g_counts[i] : 0;
    __syncthreads();
#pragma unroll
    for (int off = 256; off > 0; off >>= 1) {
        if (t < off) s[t] += s[t + off];
        __syncthreads();
    }
    if (t == 0) g_chunksum[b] = s[0];
}

// S3: per-chunk exclusive scan; chunk base computed inline (merged scan2):
// each block reduces chunksum[0..b-1] itself (196 tiny loads, L2-hot).
__global__ __launch_bounds__(512)
void scan3_kernel() {
    __shared__ int s[512];
    __shared__ int sbase[1];
    int t = threadIdx.x, b = blockIdx.x;
    int i = b * 512 + t;
    int v = (i < NN) ? g_counts[i] : 0;
    s[t] = v;

    // inline scan2: base = sum of chunksum[0..b-1], via warp 0 reduction
    if (t < 32) {
        int part = 0;
        for (int c = t; c < b; c += 32) part += g_chunksum[c];
#pragma unroll
        for (int off = 16; off > 0; off >>= 1)
            part += __shfl_xor_sync(0xffffffffu, part, off);
        if (t == 0) sbase[0] = part;
    }
    __syncthreads();
#pragma unroll
    for (int off = 1; off < 512; off <<= 1) {
        int a = (t >= off) ? s[t - off] : 0;
        __syncthreads();
        s[t] += a;
        __syncthreads();
    }
    if (i < NN) {
        int excl = s[t] - v + sbase[0];
        g_rowstart[i] = excl;
        g_cursor[i]   = excl;
    }
}

__global__ void fill_kernel(const int* __restrict__ erow, const int* __restrict__ ecol,
                            const float* __restrict__ evals) {
    int e = blockIdx.x * blockDim.x + threadIdx.x;
    if (e < NE) {
        int r = __ldg(&erow[e]);
        int pos = atomicAdd(&g_cursor[r], 1);
        g_packed[pos] = make_int2(__ldg(&ecol[e]), __float_as_int(__ldg(&evals[e])));
    }
}

// ---------------------------------------------------------------------------
// Pull: 2 rows per warp, 16 lanes per row, float4 per lane.
// Each half-warp serves one row: cooperative load of 16 (col,val) entries,
// shfl-broadcast within the half, LDG.128 gather from support, fp32 FFMA
// accumulate, single plain float4 store (bias fused, no atomics).
// Inner loop is warp-uniform (padded to the pair's max count; pad lanes carry
// v=0 against support row 0 — harmless, L2-hot).
// ---------------------------------------------------------------------------
__global__ __launch_bounds__(256)
void pull_kernel(const float* __restrict__ bias, float* __restrict__ out) {
    int warp = (blockIdx.x * 256 + threadIdx.x) >> 5;
    if (warp >= NN / 2) return;          // NN even: rows exact
    int lane = threadIdx.x & 31;
    int half = lane >> 4;                // 0 or 1
    int sub  = lane & 15;                // 0..15

    const int row   = warp * 2 + half;
    const int start = g_rowstart[row];
    const int len   = g_counts[row];
    const int lenm  = max(len, __shfl_xor_sync(0xffffffffu, len, 16));
    const int2* __restrict__ plist = g_packed + start;
    const int fo = sub * 4;
    const int hb = half << 4;

    float4 acc = *(const float4*)&bias[fo];

    for (int base = 0; base < lenm; base += 16) {
        int m  = len - base;                       // this half's valid count
        int mm = lenm - base; mm = mm < 16 ? mm : 16;  // warp-uniform bound
        int2 p = make_int2(0, 0);
        if (sub < m) p = plist[base + sub];

        int j = 0;
        for (; j + 4 <= mm; j += 4) {
            int c0 = __shfl_sync(0xffffffffu, p.x, hb + j + 0);
            int c1 = __shfl_sync(0xffffffffu, p.x, hb + j + 1);
            int c2 = __shfl_sync(0xffffffffu, p.x, hb + j + 2);
            int c3 = __shfl_sync(0xffffffffu, p.x, hb + j + 3);

            float4 s0 = *(const float4*)&g_support[(size_t)c0 * OUTF + fo];
            float4 s1 = *(const float4*)&g_support[(size_t)c1 * OUTF + fo];
            float4 s2 = *(const float4*)&g_support[(size_t)c2 * OUTF + fo];
            float4 s3 = *(const float4*)&g_support[(size_t)c3 * OUTF + fo];

            float v0 = __int_as_float(__shfl_sync(0xffffffffu, p.y, hb + j + 0));
            float v1 = __int_as_float(__shfl_sync(0xffffffffu, p.y, hb + j + 1));
            float v2 = __int_as_float(__shfl_sync(0xffffffffu, p.y, hb + j + 2));
            float v3 = __int_as_float(__shfl_sync(0xffffffffu, p.y, hb + j + 3));

            acc.x += s0.x * v0; acc.y += s0.y * v0; acc.z += s0.z * v0; acc.w += s0.w * v0;
            acc.x += s1.x * v1; acc.y += s1.y * v1; acc.z += s1.z * v1; acc.w += s1.w * v1;
            acc.x += s2.x * v2; acc.y += s2.y * v2; acc.z += s2.z * v2; acc.w += s2.w * v2;
            acc.x += s3.x * v3; acc.y += s3.y * v3; acc.z += s3.z * v3; acc.w += s3.w * v3;
        }
        for (; j < mm; j++) {
            int   c = __shfl_sync(0xffffffffu, p.x, hb + j);
            float v = __int_as_float(__shfl_sync(0xffffffffu, p.y, hb + j));
            float4 s = *(const float4*)&g_support[(size_t)c * OUTF + fo];
            acc.x += s.x * v; acc.y += s.y * v; acc.z += s.z * v; acc.w += s.w * v;
        }
    }

    *(float4*)&out[(size_t)row * OUTF + fo] = acc;
}

// ---------------------------------------------------------------------------
extern "C" void kernel_launch(void* const* d_in, const int* in_sizes, int n_in,
                              void* d_out, int out_size) {
    const float* x     = (const float*)d_in[0];   // [100000,128]
    const float* w     = (const float*)d_in[1];   // [128,64]
    const float* bias  = (const float*)d_in[2];   // [64]
    const int*   erow  = (const int*)  d_in[3];   // [1.6M]
    const int*   ecol  = (const int*)  d_in[4];   // [1.6M]
    const float* evals = (const float*)d_in[5];   // [1.6M]
    float* out = (float*)d_out;                   // [100000,64]

    const int n = in_sizes[0] / INF_;             // 100000

    // support = X @ W (SIMT fp32) + fused zeroing of counters
    gemm_kernel<<<(n + 63) / 64, 256>>>(x, w, n);

    // Counting sort of edges by destination row
    hist_kernel<<<(NE + 255) / 256, 256>>>(erow);
    scan1_kernel<<<NCHUNK, 512>>>();
    scan3_kernel<<<NCHUNK, 512>>>();
    fill_kernel<<<(NE + 255) / 256, 256>>>(erow, ecol, evals);

    // Pull: out[row] = bias + sum(support[col] * val)
    {
        int warps = NN / 2;                        // 50000
        int blocks = (warps * 32 + 255) / 256;     // 6250
        pull_kernel<<<blocks, 256>>>(bias, out);
    }
}